// round 1
// baseline (speedup 1.0000x reference)
#include <cuda_runtime.h>

#define N_NODES 10000
#define NB 32            // batch
#define NF 66            // IN_SIZE + UNITS
#define NU 64
#define NU2 128
#define ROWW 2112        // NF * NB floats per node row
#define ROWW4 528        // float4 per node row
#define NNZ_MAX 330000
#define X0_ELEMS (N_NODES * ROWW)   // 21,120,000
#define V_STRIDE 1280000            // N_NODES * NU2 (per batch)
#define S_STRIDE 640000             // N_NODES * NU  (per batch)

__device__ float g_X0[X0_ELEMS];
__device__ float g_X1[X0_ELEMS];
__device__ float g_V[NB * N_NODES * NU2];
__device__ int   g_cnt[N_NODES];
__device__ int   g_cur[N_NODES];
__device__ int   g_rowptr[N_NODES + 1];
__device__ int   g_col[NNZ_MAX];
__device__ float g_val[NNZ_MAX];

// ---------------- CSR build ----------------

__global__ void k_zero() {
    int i = blockIdx.x * blockDim.x + threadIdx.x;
    if (i < N_NODES) { g_cnt[i] = 0; g_cur[i] = 0; }
}

__global__ void k_hist(const int* __restrict__ rows, int nnz) {
    int i = blockIdx.x * blockDim.x + threadIdx.x;
    if (i < nnz) atomicAdd(&g_cnt[rows[i]], 1);
}

__global__ void k_scan() {
    __shared__ int s[1024];
    int tid = threadIdx.x;
    int loc[10];
    int sum = 0;
#pragma unroll
    for (int k = 0; k < 10; k++) {
        int i = tid * 10 + k;
        int v = (i < N_NODES) ? g_cnt[i] : 0;
        loc[k] = v; sum += v;
    }
    s[tid] = sum;
    __syncthreads();
    for (int d = 1; d < 1024; d <<= 1) {
        int v = (tid >= d) ? s[tid - d] : 0;
        __syncthreads();
        s[tid] += v;
        __syncthreads();
    }
    int run = s[tid] - sum;  // exclusive prefix
#pragma unroll
    for (int k = 0; k < 10; k++) {
        int i = tid * 10 + k;
        if (i < N_NODES) g_rowptr[i] = run;
        run += loc[k];
    }
    if (tid == 1023) g_rowptr[N_NODES] = run;
}

__global__ void k_scatter(const int* __restrict__ rows, const int* __restrict__ cols,
                          const float* __restrict__ vals, int nnz) {
    int i = blockIdx.x * blockDim.x + threadIdx.x;
    if (i < nnz) {
        int r = rows[i];
        int p = g_rowptr[r] + atomicAdd(&g_cur[r], 1);
        g_col[p] = cols[i];
        g_val[p] = vals[i];
    }
}

// ---------------- X0 builders ----------------
// layout: g_X0[n*2112 + b*66 + f], f<2 -> inputs, else state(-like)

__global__ void k_build0(const float* __restrict__ inputs, const float* __restrict__ state) {
    int idx = blockIdx.x * 256 + threadIdx.x;
    if (idx >= X0_ELEMS) return;
    int n = idx / ROWW;
    int rem = idx - n * ROWW;
    int b = rem / NF;
    int f = rem - b * NF;
    float v;
    if (f < 2) v = inputs[b * 20000 + n * 2 + f];
    else       v = state[b * S_STRIDE + n * NU + (f - 2)];
    g_X0[idx] = v;
}

__global__ void k_build1(const float* __restrict__ inputs, const float* __restrict__ state) {
    int idx = blockIdx.x * 256 + threadIdx.x;
    if (idx >= X0_ELEMS) return;
    int n = idx / ROWW;
    int rem = idx - n * ROWW;
    int b = rem / NF;
    int f = rem - b * NF;
    float v;
    if (f < 2) {
        v = inputs[b * 20000 + n * 2 + f];
    } else {
        int j = n * NU + (f - 2);          // flat index into first half of V (r) and state
        v = g_V[(size_t)b * V_STRIDE + j] * state[(size_t)b * S_STRIDE + j];
    }
    g_X0[idx] = v;
}

// ---------------- SpMM: one block per output row ----------------

__global__ void k_spmm() {
    const float4* __restrict__ X = (const float4*)g_X0;
    float4* __restrict__ Y = (float4*)g_X1;
    int n = blockIdx.x;
    int tid = threadIdx.x;   // 176 threads, 3 float4 each -> 528
    __shared__ int   scol[128];
    __shared__ float sval[128];
    float4 a0 = make_float4(0.f, 0.f, 0.f, 0.f), a1 = a0, a2 = a0;
    int beg = g_rowptr[n], end = g_rowptr[n + 1];
    for (int base = beg; base < end; base += 128) {
        int cnt = min(128, end - base);
        __syncthreads();
        if (tid < cnt) { scol[tid] = g_col[base + tid]; sval[tid] = g_val[base + tid]; }
        __syncthreads();
#pragma unroll 4
        for (int e = 0; e < cnt; e++) {
            const float4* src = X + (size_t)scol[e] * ROWW4;
            float v = sval[e];
            float4 x0 = src[tid];
            float4 x1 = src[tid + 176];
            float4 x2 = src[tid + 352];
            a0.x = fmaf(v, x0.x, a0.x); a0.y = fmaf(v, x0.y, a0.y);
            a0.z = fmaf(v, x0.z, a0.z); a0.w = fmaf(v, x0.w, a0.w);
            a1.x = fmaf(v, x1.x, a1.x); a1.y = fmaf(v, x1.y, a1.y);
            a1.z = fmaf(v, x1.z, a1.z); a1.w = fmaf(v, x1.w, a1.w);
            a2.x = fmaf(v, x2.x, a2.x); a2.y = fmaf(v, x2.y, a2.y);
            a2.z = fmaf(v, x2.z, a2.z); a2.w = fmaf(v, x2.w, a2.w);
        }
    }
    float4* dst = Y + (size_t)n * ROWW4;
    dst[tid] = a0; dst[tid + 176] = a1; dst[tid + 352] = a2;
}

// ---------------- GEMM1: [B*N, 66] @ [66,128] + b1, sigmoid -> V ----------------

__device__ __forceinline__ float sigf(float x) { return 1.0f / (1.0f + __expf(-x)); }

__global__ void k_gemm1(const float* __restrict__ w, const float* __restrict__ bias) {
    __shared__ float xs[32][68];
    __shared__ float ws[NF * NU2];
    int tid = threadIdx.x;           // 256
    int g0 = blockIdx.x * 32;        // rows g0..g0+31 == node blockIdx.x, b = 0..31
    for (int i = tid; i < NF * NU2; i += 256) ws[i] = w[i];
    const float* src = g_X1 + (size_t)g0 * NF;
    for (int i = tid; i < 32 * NF; i += 256) {
        int r = i / NF, f = i - r * NF;
        xs[r][f] = src[i];
    }
    __syncthreads();
    int tx = tid & 31, ty = tid >> 5;
    float acc[4][4] = {};
    for (int f = 0; f < NF; f++) {
        float4 w4 = *(const float4*)&ws[f * NU2 + tx * 4];
        float a[4];
#pragma unroll
        for (int i = 0; i < 4; i++) a[i] = xs[ty * 4 + i][f];
#pragma unroll
        for (int i = 0; i < 4; i++) {
            acc[i][0] = fmaf(a[i], w4.x, acc[i][0]);
            acc[i][1] = fmaf(a[i], w4.y, acc[i][1]);
            acc[i][2] = fmaf(a[i], w4.z, acc[i][2]);
            acc[i][3] = fmaf(a[i], w4.w, acc[i][3]);
        }
    }
    float4 bb = *(const float4*)&bias[tx * 4];
    int n = blockIdx.x;
#pragma unroll
    for (int i = 0; i < 4; i++) {
        int b = ty * 4 + i;
        float4 o;
        o.x = sigf(acc[i][0] + bb.x);
        o.y = sigf(acc[i][1] + bb.y);
        o.z = sigf(acc[i][2] + bb.z);
        o.w = sigf(acc[i][3] + bb.w);
        *(float4*)&g_V[(size_t)b * V_STRIDE + n * NU2 + tx * 4] = o;
    }
}

// ---------------- GEMM2: [B*N,66]@[66,64]+b2, relu, GRU combine -> out ----------------

__global__ void k_gemm2(const float* __restrict__ w, const float* __restrict__ bias,
                        const float* __restrict__ state, float* __restrict__ out) {
    __shared__ float xs[64][68];
    __shared__ float ws[NF * NU];
    int tid = threadIdx.x;       // 256
    int g0 = blockIdx.x * 64;
    for (int i = tid; i < NF * NU; i += 256) ws[i] = w[i];
    const float* src = g_X1 + (size_t)g0 * NF;
    for (int i = tid; i < 64 * NF; i += 256) {
        int r = i / NF, f = i - r * NF;
        xs[r][f] = src[i];
    }
    __syncthreads();
    int tx = tid & 15, ty = tid >> 4;
    float acc[4][4] = {};
    for (int f = 0; f < NF; f++) {
        float4 w4 = *(const float4*)&ws[f * NU + tx * 4];
        float a[4];
#pragma unroll
        for (int i = 0; i < 4; i++) a[i] = xs[ty * 4 + i][f];
#pragma unroll
        for (int i = 0; i < 4; i++) {
            acc[i][0] = fmaf(a[i], w4.x, acc[i][0]);
            acc[i][1] = fmaf(a[i], w4.y, acc[i][1]);
            acc[i][2] = fmaf(a[i], w4.z, acc[i][2]);
            acc[i][3] = fmaf(a[i], w4.w, acc[i][3]);
        }
    }
    float4 bb = *(const float4*)&bias[tx * 4];
#pragma unroll
    for (int i = 0; i < 4; i++) {
        int g = g0 + ty * 4 + i;
        int n = g >> 5, b = g & 31;
        int j = n * NU + tx * 4;
        float4 u4 = *(const float4*)&g_V[(size_t)b * V_STRIDE + S_STRIDE + j];
        float4 s4 = *(const float4*)&state[(size_t)b * S_STRIDE + j];
        float4 c;
        c.x = fmaxf(acc[i][0] + bb.x, 0.0f);
        c.y = fmaxf(acc[i][1] + bb.y, 0.0f);
        c.z = fmaxf(acc[i][2] + bb.z, 0.0f);
        c.w = fmaxf(acc[i][3] + bb.w, 0.0f);
        float4 o;
        o.x = u4.x * s4.x + (1.0f - u4.x) * c.x;
        o.y = u4.y * s4.y + (1.0f - u4.y) * c.y;
        o.z = u4.z * s4.z + (1.0f - u4.z) * c.z;
        o.w = u4.w * s4.w + (1.0f - u4.w) * c.w;
        *(float4*)&out[(size_t)b * S_STRIDE + j] = o;
    }
}

// ---------------- launch ----------------

extern "C" void kernel_launch(void* const* d_in, const int* in_sizes, int n_in,
                              void* d_out, int out_size) {
    const float* inputs = (const float*)d_in[0];
    const float* state  = (const float*)d_in[1];
    const int*   m_rows = (const int*)d_in[2];
    const int*   m_cols = (const int*)d_in[3];
    const float* m_vals = (const float*)d_in[4];
    const float* w1     = (const float*)d_in[5];
    const float* b1     = (const float*)d_in[6];
    const float* w2     = (const float*)d_in[7];
    const float* b2     = (const float*)d_in[8];
    float* out = (float*)d_out;
    int nnz = in_sizes[2];

    k_zero<<<(N_NODES + 255) / 256, 256>>>();
    k_hist<<<(nnz + 255) / 256, 256>>>(m_rows, nnz);
    k_scan<<<1, 1024>>>();
    k_scatter<<<(nnz + 255) / 256, 256>>>(m_rows, m_cols, m_vals, nnz);

    // gc1
    k_build0<<<(X0_ELEMS + 255) / 256, 256>>>(inputs, state);
    k_spmm<<<N_NODES, 176>>>();
    k_gemm1<<<N_NODES, 256>>>(w1, b1);

    // gc2 (input rebuilt from r*state into g_X0)
    k_build1<<<(X0_ELEMS + 255) / 256, 256>>>(inputs, state);
    k_spmm<<<N_NODES, 176>>>();
    k_gemm2<<<(NB * N_NODES) / 64, 256>>>(w2, b2, state, out);
}

// round 2
// speedup vs baseline: 1.1677x; 1.1677x over previous
#include <cuda_runtime.h>
#include <cuda_fp16.h>

#define N_NODES 10000
#define NB 32
#define NF 66
#define NU 64
#define NU2 128
#define ROWW 2112            // NF*NB floats (or halves) per node row
#define ROWQ 264             // uint4 (8 halves) per node row
#define NNZ_MAX 330000
#define X0_ELEMS (N_NODES * ROWW)
#define S_STRIDE 640000      // N*NU per batch

typedef unsigned long long ull;

__device__ __half g_X0h[X0_ELEMS];          // 42.2 MB, fp16 gather source
__device__ float  g_X1[X0_ELEMS];           // 84.5 MB, spmm output
__device__ float  g_U[NB * S_STRIDE];       // 81.9 MB, update gate
__device__ int    g_cnt[N_NODES];
__device__ int    g_cur[N_NODES];
__device__ int    g_rowptr[N_NODES + 1];
__device__ int    g_col[NNZ_MAX];
__device__ float  g_val[NNZ_MAX];

// ---------- f32x2 helpers ----------
__device__ __forceinline__ ull pk2(float lo, float hi) {
    ull r; asm("mov.b64 %0, {%1, %2};" : "=l"(r) : "f"(lo), "f"(hi)); return r;
}
__device__ __forceinline__ void upk2(ull v, float& lo, float& hi) {
    asm("mov.b64 {%0, %1}, %2;" : "=f"(lo), "=f"(hi) : "l"(v));
}
__device__ __forceinline__ void fma2(ull& d, ull a, ull b) {
    asm("fma.rn.f32x2 %0, %1, %2, %0;" : "+l"(d) : "l"(a), "l"(b));
}
__device__ __forceinline__ float sigf(float x) { return 1.0f / (1.0f + __expf(-x)); }

// ---------------- CSR build ----------------
__global__ void k_zero() {
    int i = blockIdx.x * blockDim.x + threadIdx.x;
    if (i < N_NODES) { g_cnt[i] = 0; g_cur[i] = 0; }
}
__global__ void k_hist(const int* __restrict__ rows, int nnz) {
    int i = blockIdx.x * blockDim.x + threadIdx.x;
    if (i < nnz) atomicAdd(&g_cnt[rows[i]], 1);
}
__global__ void k_scan() {
    __shared__ int s[1024];
    int tid = threadIdx.x;
    int loc[10];
    int sum = 0;
#pragma unroll
    for (int k = 0; k < 10; k++) {
        int i = tid * 10 + k;
        int v = (i < N_NODES) ? g_cnt[i] : 0;
        loc[k] = v; sum += v;
    }
    s[tid] = sum;
    __syncthreads();
    for (int d = 1; d < 1024; d <<= 1) {
        int v = (tid >= d) ? s[tid - d] : 0;
        __syncthreads();
        s[tid] += v;
        __syncthreads();
    }
    int run = s[tid] - sum;
#pragma unroll
    for (int k = 0; k < 10; k++) {
        int i = tid * 10 + k;
        if (i < N_NODES) g_rowptr[i] = run;
        run += loc[k];
    }
    if (tid == 1023) g_rowptr[N_NODES] = run;
}
__global__ void k_scatter(const int* __restrict__ rows, const int* __restrict__ cols,
                          const float* __restrict__ vals, int nnz) {
    int i = blockIdx.x * blockDim.x + threadIdx.x;
    if (i < nnz) {
        int r = rows[i];
        int p = g_rowptr[r] + atomicAdd(&g_cur[r], 1);
        g_col[p] = cols[i];
        g_val[p] = vals[i];
    }
}

// ---------------- X0h builder (gc1 input) ----------------
__global__ void k_build0h(const float* __restrict__ inputs, const float* __restrict__ state) {
    int idx = blockIdx.x * 256 + threadIdx.x;
    if (idx >= X0_ELEMS) return;
    int n = idx / ROWW;
    int rem = idx - n * ROWW;
    int b = rem / NF;
    int f = rem - b * NF;
    float v = (f < 2) ? inputs[b * 20000 + n * 2 + f]
                      : state[(size_t)b * S_STRIDE + n * NU + (f - 2)];
    g_X0h[idx] = __float2half(v);
}

// ---------------- SpMM (fp16 gather, fp32 accum) ----------------
__global__ void k_spmm_h() {
    const uint4* __restrict__ X = (const uint4*)g_X0h;
    int n = blockIdx.x;
    int t = threadIdx.x;                 // 264 threads, 1 uint4 (8 halves) each
    __shared__ int   scol[128];
    __shared__ float sval[128];
    float a0 = 0.f, a1 = 0.f, a2 = 0.f, a3 = 0.f, a4 = 0.f, a5 = 0.f, a6 = 0.f, a7 = 0.f;
    int beg = g_rowptr[n], end = g_rowptr[n + 1];
    for (int base = beg; base < end; base += 128) {
        int cnt = min(128, end - base);
        __syncthreads();
        if (t < cnt) { scol[t] = g_col[base + t]; sval[t] = g_val[base + t]; }
        __syncthreads();
#pragma unroll 2
        for (int e = 0; e < cnt; e++) {
            const uint4* src = X + (size_t)scol[e] * ROWQ;
            float v = sval[e];
            uint4 q = src[t];
            float2 f0 = __half22float2(*(__half2*)&q.x);
            float2 f1 = __half22float2(*(__half2*)&q.y);
            float2 f2 = __half22float2(*(__half2*)&q.z);
            float2 f3 = __half22float2(*(__half2*)&q.w);
            a0 = fmaf(v, f0.x, a0); a1 = fmaf(v, f0.y, a1);
            a2 = fmaf(v, f1.x, a2); a3 = fmaf(v, f1.y, a3);
            a4 = fmaf(v, f2.x, a4); a5 = fmaf(v, f2.y, a5);
            a6 = fmaf(v, f3.x, a6); a7 = fmaf(v, f3.y, a7);
        }
    }
    float* dst = g_X1 + (size_t)n * ROWW + t * 8;
    __stcs((float4*)dst,       make_float4(a0, a1, a2, a3));
    __stcs((float4*)(dst + 4), make_float4(a4, a5, a6, a7));
}

// ---------------- GEMM1 fused: X1@w1+b1, sigmoid; write r*state (fp16) or u ----------------
// Block B0 covers nodes 2*B0, 2*B0+1 (64 rows x 128 cols). 128 threads, 8x8 tile each.
__global__ void k_gemm1f(const float* __restrict__ w, const float* __restrict__ bias,
                         const float* __restrict__ state) {
    __shared__ float xs[NF][64];         // transposed [f][row]
    __shared__ float ws[NF * NU2];
    int tid = threadIdx.x;               // 128
    int B0 = blockIdx.x;                 // 0..4999
    for (int i = tid; i < NF * NU2; i += 128) ws[i] = w[i];
    const float* src = g_X1 + (size_t)B0 * 4224;
    for (int i = tid; i < 4224; i += 128) {
        int r = i / NF, f = i - r * NF;
        xs[f][r] = __ldcs(src + i);
    }
    __syncthreads();
    int tx = tid & 15, ty = tid >> 4;    // tx: 8 cols, ty: 8 rows
    ull acc[4][8];
#pragma unroll
    for (int i = 0; i < 4; i++)
#pragma unroll
        for (int j = 0; j < 8; j++) acc[i][j] = 0ull;

#pragma unroll 2
    for (int f = 0; f < NF; f++) {
        ull a[4];
#pragma unroll
        for (int rp = 0; rp < 4; rp++)
            a[rp] = *(const ull*)&xs[f][ty * 8 + rp * 2];
        float4 w0 = *(const float4*)&ws[f * NU2 + tx * 8];
        float4 w1 = *(const float4*)&ws[f * NU2 + tx * 8 + 4];
        ull wd[8];
        wd[0] = pk2(w0.x, w0.x); wd[1] = pk2(w0.y, w0.y);
        wd[2] = pk2(w0.z, w0.z); wd[3] = pk2(w0.w, w0.w);
        wd[4] = pk2(w1.x, w1.x); wd[5] = pk2(w1.y, w1.y);
        wd[6] = pk2(w1.z, w1.z); wd[7] = pk2(w1.w, w1.w);
#pragma unroll
        for (int rp = 0; rp < 4; rp++)
#pragma unroll
            for (int j = 0; j < 8; j++) fma2(acc[rp][j], a[rp], wd[j]);
    }

    float bz[8];
    {
        float4 bb0 = *(const float4*)&bias[tx * 8];
        float4 bb1 = *(const float4*)&bias[tx * 8 + 4];
        bz[0] = bb0.x; bz[1] = bb0.y; bz[2] = bb0.z; bz[3] = bb0.w;
        bz[4] = bb1.x; bz[5] = bb1.y; bz[6] = bb1.z; bz[7] = bb1.w;
    }
    bool rside = (B0 < 2500);
#pragma unroll
    for (int rp = 0; rp < 4; rp++) {
#pragma unroll
        for (int h = 0; h < 2; h++) {
            int r = ty * 8 + rp * 2 + h;         // row within block (0..63)
            int nn = 2 * B0 + (r >> 5);          // node
            int b = r & 31;                      // batch
            float v[8];
#pragma unroll
            for (int j = 0; j < 8; j++) {
                float lo, hi; upk2(acc[rp][j], lo, hi);
                v[j] = sigf((h ? hi : lo) + bz[j]);
            }
            if (rside) {
                int t = 2 * nn + (tx >> 3);
                int c = (tx & 7) * 8;
                const float* sp = state + (size_t)b * S_STRIDE + t * 64 + c;
                float4 s0 = *(const float4*)sp;
                float4 s1 = *(const float4*)(sp + 4);
                __half2* dst = (__half2*)&g_X0h[(size_t)t * ROWW + b * NF + 2 + c];
                dst[0] = __floats2half2_rn(v[0] * s0.x, v[1] * s0.y);
                dst[1] = __floats2half2_rn(v[2] * s0.z, v[3] * s0.w);
                dst[2] = __floats2half2_rn(v[4] * s1.x, v[5] * s1.y);
                dst[3] = __floats2half2_rn(v[6] * s1.z, v[7] * s1.w);
            } else {
                float* up = g_U + (size_t)b * S_STRIDE + (nn - 5000) * 128 + tx * 8;
                *(float4*)up       = make_float4(v[0], v[1], v[2], v[3]);
                *(float4*)(up + 4) = make_float4(v[4], v[5], v[6], v[7]);
            }
        }
    }
}

// ---------------- GEMM2 + GRU combine ----------------
// Block covers 64 rows (2 nodes) x 64 cols. 128 threads, 8x4 tile each.
__global__ void k_gemm2(const float* __restrict__ w, const float* __restrict__ bias,
                        const float* __restrict__ state, float* __restrict__ out) {
    __shared__ float xs[NF][64];
    __shared__ float ws[NF * NU];
    int tid = threadIdx.x;               // 128
    int g0 = blockIdx.x * 64;
    for (int i = tid; i < NF * NU; i += 128) ws[i] = w[i];
    const float* src = g_X1 + (size_t)g0 * NF;
    for (int i = tid; i < 4224; i += 128) {
        int r = i / NF, f = i - r * NF;
        xs[f][r] = __ldcs(src + i);
    }
    __syncthreads();
    int tx = tid & 15, ty = tid >> 4;    // tx: 4 cols, ty: 8 rows
    ull acc[4][4];
#pragma unroll
    for (int i = 0; i < 4; i++)
#pragma unroll
        for (int j = 0; j < 4; j++) acc[i][j] = 0ull;

#pragma unroll 2
    for (int f = 0; f < NF; f++) {
        ull a[4];
#pragma unroll
        for (int rp = 0; rp < 4; rp++)
            a[rp] = *(const ull*)&xs[f][ty * 8 + rp * 2];
        float4 w4 = *(const float4*)&ws[f * NU + tx * 4];
        ull wd[4];
        wd[0] = pk2(w4.x, w4.x); wd[1] = pk2(w4.y, w4.y);
        wd[2] = pk2(w4.z, w4.z); wd[3] = pk2(w4.w, w4.w);
#pragma unroll
        for (int rp = 0; rp < 4; rp++)
#pragma unroll
            for (int j = 0; j < 4; j++) fma2(acc[rp][j], a[rp], wd[j]);
    }

    float4 bb = *(const float4*)&bias[tx * 4];
    float bz[4] = {bb.x, bb.y, bb.z, bb.w};
#pragma unroll
    for (int rp = 0; rp < 4; rp++) {
#pragma unroll
        for (int h = 0; h < 2; h++) {
            int r = ty * 8 + rp * 2 + h;
            int g = g0 + r;
            int n = g >> 5, b = g & 31;
            size_t j = (size_t)b * S_STRIDE + n * 64 + tx * 4;
            float c[4];
#pragma unroll
            for (int q = 0; q < 4; q++) {
                float lo, hi; upk2(acc[rp][q], lo, hi);
                c[q] = fmaxf((h ? hi : lo) + bz[q], 0.0f);
            }
            float4 u4 = *(const float4*)&g_U[j];
            float4 s4 = *(const float4*)&state[j];
            float4 o;
            o.x = u4.x * s4.x + (1.0f - u4.x) * c[0];
            o.y = u4.y * s4.y + (1.0f - u4.y) * c[1];
            o.z = u4.z * s4.z + (1.0f - u4.z) * c[2];
            o.w = u4.w * s4.w + (1.0f - u4.w) * c[3];
            *(float4*)&out[j] = o;
        }
    }
}

// ---------------- launch ----------------
extern "C" void kernel_launch(void* const* d_in, const int* in_sizes, int n_in,
                              void* d_out, int out_size) {
    const float* inputs = (const float*)d_in[0];
    const float* state  = (const float*)d_in[1];
    const int*   m_rows = (const int*)d_in[2];
    const int*   m_cols = (const int*)d_in[3];
    const float* m_vals = (const float*)d_in[4];
    const float* w1     = (const float*)d_in[5];
    const float* b1     = (const float*)d_in[6];
    const float* w2     = (const float*)d_in[7];
    const float* b2     = (const float*)d_in[8];
    float* out = (float*)d_out;
    int nnz = in_sizes[2];

    k_zero<<<(N_NODES + 255) / 256, 256>>>();
    k_hist<<<(nnz + 255) / 256, 256>>>(m_rows, nnz);
    k_scan<<<1, 1024>>>();
    k_scatter<<<(nnz + 255) / 256, 256>>>(m_rows, m_cols, m_vals, nnz);

    k_build0h<<<(X0_ELEMS + 255) / 256, 256>>>(inputs, state);
    k_spmm_h<<<N_NODES, ROWQ>>>();
    k_gemm1f<<<N_NODES / 2, 128>>>(w1, b1, state);   // writes r*state into g_X0h, u into g_U
    k_spmm_h<<<N_NODES, ROWQ>>>();
    k_gemm2<<<(NB * N_NODES) / 64, 128>>>(w2, b2, state, out);
}

// round 3
// speedup vs baseline: 1.7196x; 1.4727x over previous
#include <cuda_runtime.h>
#include <cuda_fp16.h>

#define N_NODES 10000
#define NB 32
#define NF 66
#define NU 64
#define NU2 128
#define SROW 2048            // halves per node state-row
#define SROWQ 256            // uint4 per state-row (8 warps exactly)
#define NNZ_MAX 330000
#define XS_ELEMS (N_NODES * SROW)
#define S_STRIDE 640000      // N*NU per batch

typedef unsigned long long ull;

__device__ __half  g_XSh[XS_ELEMS];        // 41 MB gather source (state part)
__device__ __half  g_X1h[XS_ELEMS];        // 41 MB spmm output
__device__ float2  g_XI[N_NODES * NB];     // 2.56 MB inputs-part gather source (fp32)
__device__ float2  g_YI[N_NODES * NB];     // 2.56 MB inputs-part spmm result (reused)
__device__ __half  g_Uh[NB * S_STRIDE];    // 41 MB update gate
__device__ int     g_cnt[N_NODES];
__device__ int     g_cur[N_NODES];
__device__ int     g_rowptr[N_NODES + 1];
__device__ int     g_col[NNZ_MAX];
__device__ float   g_val[NNZ_MAX];

// ---------- f32x2 helpers ----------
__device__ __forceinline__ ull pk2(float lo, float hi) {
    ull r; asm("mov.b64 %0, {%1, %2};" : "=l"(r) : "f"(lo), "f"(hi)); return r;
}
__device__ __forceinline__ void upk2(ull v, float& lo, float& hi) {
    asm("mov.b64 {%0, %1}, %2;" : "=f"(lo), "=f"(hi) : "l"(v));
}
__device__ __forceinline__ void fma2(ull& d, ull a, ull b) {
    asm("fma.rn.f32x2 %0, %1, %2, %0;" : "+l"(d) : "l"(a), "l"(b));
}
__device__ __forceinline__ float sigf(float x) { return 1.0f / (1.0f + __expf(-x)); }

// ---------------- CSR build ----------------
__global__ void k_zero() {
    int i = blockIdx.x * blockDim.x + threadIdx.x;
    if (i < N_NODES) { g_cnt[i] = 0; g_cur[i] = 0; }
}
__global__ void k_hist(const int* __restrict__ rows, int nnz) {
    int i = blockIdx.x * blockDim.x + threadIdx.x;
    if (i < nnz) atomicAdd(&g_cnt[rows[i]], 1);
}
__global__ void k_scan() {
    __shared__ int s[1024];
    int tid = threadIdx.x;
    int loc[10];
    int sum = 0;
#pragma unroll
    for (int k = 0; k < 10; k++) {
        int i = tid * 10 + k;
        int v = (i < N_NODES) ? g_cnt[i] : 0;
        loc[k] = v; sum += v;
    }
    s[tid] = sum;
    __syncthreads();
    for (int d = 1; d < 1024; d <<= 1) {
        int v = (tid >= d) ? s[tid - d] : 0;
        __syncthreads();
        s[tid] += v;
        __syncthreads();
    }
    int run = s[tid] - sum;
#pragma unroll
    for (int k = 0; k < 10; k++) {
        int i = tid * 10 + k;
        if (i < N_NODES) g_rowptr[i] = run;
        run += loc[k];
    }
    if (tid == 1023) g_rowptr[N_NODES] = run;
}
__global__ void k_scatter(const int* __restrict__ rows, const int* __restrict__ cols,
                          const float* __restrict__ vals, int nnz) {
    int i = blockIdx.x * blockDim.x + threadIdx.x;
    if (i < nnz) {
        int r = rows[i];
        int p = g_rowptr[r] + atomicAdd(&g_cur[r], 1);
        g_col[p] = cols[i];
        g_val[p] = vals[i];
    }
}

// ---------------- builders ----------------
__global__ void k_buildXS(const float* __restrict__ state) {
    int id = blockIdx.x * 256 + threadIdx.x;          // one uint4 (8 halves)
    if (id >= XS_ELEMS / 8) return;
    int i8 = id * 8;
    int n = i8 >> 11;
    int b = (i8 >> 6) & 31;
    int u = i8 & 63;
    const float* sp = state + (size_t)b * S_STRIDE + n * 64 + u;
    float4 s0 = *(const float4*)sp;
    float4 s1 = *(const float4*)(sp + 4);
    uint4 o;
    ((__half2*)&o)[0] = __floats2half2_rn(s0.x, s0.y);
    ((__half2*)&o)[1] = __floats2half2_rn(s0.z, s0.w);
    ((__half2*)&o)[2] = __floats2half2_rn(s1.x, s1.y);
    ((__half2*)&o)[3] = __floats2half2_rn(s1.z, s1.w);
    ((uint4*)g_XSh)[id] = o;
}
__global__ void k_buildXI(const float* __restrict__ inputs) {
    int id = blockIdx.x * 256 + threadIdx.x;
    if (id >= N_NODES * NB) return;
    int b = id / N_NODES, n = id - b * N_NODES;
    float2 v = *(const float2*)&inputs[b * 20000 + 2 * n];
    g_XI[n * 32 + b] = v;
}

// ---------------- SpMM (inputs part, once) ----------------
__global__ void k_spmm_in() {
    int gw = (blockIdx.x * 256 + threadIdx.x) >> 5;
    int lane = threadIdx.x & 31;
    if (gw >= N_NODES) return;
    int beg = __ldg(&g_rowptr[gw]), end = __ldg(&g_rowptr[gw + 1]);
    float2 acc = make_float2(0.f, 0.f);
    for (int e = beg; e < end; e++) {
        int c = __ldg(&g_col[e]);
        float v = __ldg(&g_val[e]);
        float2 x = g_XI[c * 32 + lane];
        acc.x = fmaf(v, x.x, acc.x);
        acc.y = fmaf(v, x.y, acc.y);
    }
    g_YI[gw * 32 + lane] = acc;
}

// ---------------- SpMM (state part, fp16 gather, fp32 accum) ----------------
__device__ __forceinline__ void acc8(float* a, uint4 q, float v) {
    float2 f0 = __half22float2(*(__half2*)&q.x);
    float2 f1 = __half22float2(*(__half2*)&q.y);
    float2 f2 = __half22float2(*(__half2*)&q.z);
    float2 f3 = __half22float2(*(__half2*)&q.w);
    a[0] = fmaf(v, f0.x, a[0]); a[1] = fmaf(v, f0.y, a[1]);
    a[2] = fmaf(v, f1.x, a[2]); a[3] = fmaf(v, f1.y, a[3]);
    a[4] = fmaf(v, f2.x, a[4]); a[5] = fmaf(v, f2.y, a[5]);
    a[6] = fmaf(v, f3.x, a[6]); a[7] = fmaf(v, f3.y, a[7]);
}

__global__ void __launch_bounds__(256) k_spmm_s() {
    const uint4* __restrict__ X = (const uint4*)g_XSh;
    int n = blockIdx.x;
    int t = threadIdx.x;
    __shared__ int   scol[256];
    __shared__ float sval[256];
    float a[8] = {0.f, 0.f, 0.f, 0.f, 0.f, 0.f, 0.f, 0.f};
    int beg = __ldg(&g_rowptr[n]), end = __ldg(&g_rowptr[n + 1]);
    for (int base = beg; base < end; base += 256) {
        int cnt = min(256, end - base);
        __syncthreads();
        if (t < cnt) { scol[t] = g_col[base + t]; sval[t] = g_val[base + t]; }
        __syncthreads();
        int e = 0;
        for (; e + 4 <= cnt; e += 4) {
            uint4 q0 = X[(size_t)scol[e + 0] * SROWQ + t];
            uint4 q1 = X[(size_t)scol[e + 1] * SROWQ + t];
            uint4 q2 = X[(size_t)scol[e + 2] * SROWQ + t];
            uint4 q3 = X[(size_t)scol[e + 3] * SROWQ + t];
            acc8(a, q0, sval[e + 0]);
            acc8(a, q1, sval[e + 1]);
            acc8(a, q2, sval[e + 2]);
            acc8(a, q3, sval[e + 3]);
        }
        for (; e < cnt; e++) {
            uint4 q = X[(size_t)scol[e] * SROWQ + t];
            acc8(a, q, sval[e]);
        }
    }
    uint4 o;
    ((__half2*)&o)[0] = __floats2half2_rn(a[0], a[1]);
    ((__half2*)&o)[1] = __floats2half2_rn(a[2], a[3]);
    ((__half2*)&o)[2] = __floats2half2_rn(a[4], a[5]);
    ((__half2*)&o)[3] = __floats2half2_rn(a[6], a[7]);
    ((uint4*)g_X1h)[(size_t)n * SROWQ + t] = o;
}

// ---------------- shared xs fill (conflict-free, padded stride 66) ----------------
__device__ __forceinline__ void fill_xs(float xs[NF][66], int tid, int B0) {
    const uint2* src = (const uint2*)(g_X1h + (size_t)B0 * 4096);
#pragma unroll
    for (int k = 0; k < 8; k++) {
        int idx4 = tid + k * 128;        // 1024 uint2 = 64 rows x 16
        int r = idx4 >> 4;
        int u = (idx4 & 15) * 4;
        uint2 q = src[idx4];
        float2 f0 = __half22float2(*(__half2*)&q.x);
        float2 f1 = __half22float2(*(__half2*)&q.y);
        xs[u + 2][r] = f0.x; xs[u + 3][r] = f0.y;
        xs[u + 4][r] = f1.x; xs[u + 5][r] = f1.y;
    }
    {   // inputs-part columns from precomputed YI
        int r = tid >> 1, f = tid & 1;
        int node = 2 * B0 + (r >> 5), b = r & 31;
        float2 y = g_YI[node * 32 + b];
        xs[f][r] = f ? y.y : y.x;
    }
}

// ---------------- GEMM1 fused: sigmoid; write r*state (fp16) or u (fp16) ----------------
__global__ void __launch_bounds__(128) k_gemm1f(const float* __restrict__ w,
                                                const float* __restrict__ bias,
                                                const float* __restrict__ state) {
    __shared__ float xs[NF][66];
    __shared__ float ws[NF * NU2];
    int tid = threadIdx.x;
    int B0 = blockIdx.x;                 // nodes 2B0, 2B0+1
    for (int i = tid; i < NF * NU2; i += 128) ws[i] = w[i];
    fill_xs(xs, tid, B0);
    __syncthreads();
    int tx = tid & 15, ty = tid >> 4;
    ull acc[4][8];
#pragma unroll
    for (int i = 0; i < 4; i++)
#pragma unroll
        for (int j = 0; j < 8; j++) acc[i][j] = 0ull;

#pragma unroll 2
    for (int f = 0; f < NF; f++) {
        ull a[4];
#pragma unroll
        for (int rp = 0; rp < 4; rp++)
            a[rp] = *(const ull*)&xs[f][ty * 8 + rp * 2];
        float4 w0 = *(const float4*)&ws[f * NU2 + tx * 8];
        float4 w1 = *(const float4*)&ws[f * NU2 + tx * 8 + 4];
        ull wd[8];
        wd[0] = pk2(w0.x, w0.x); wd[1] = pk2(w0.y, w0.y);
        wd[2] = pk2(w0.z, w0.z); wd[3] = pk2(w0.w, w0.w);
        wd[4] = pk2(w1.x, w1.x); wd[5] = pk2(w1.y, w1.y);
        wd[6] = pk2(w1.z, w1.z); wd[7] = pk2(w1.w, w1.w);
#pragma unroll
        for (int rp = 0; rp < 4; rp++)
#pragma unroll
            for (int j = 0; j < 8; j++) fma2(acc[rp][j], a[rp], wd[j]);
    }

    float bz[8];
    {
        float4 bb0 = *(const float4*)&bias[tx * 8];
        float4 bb1 = *(const float4*)&bias[tx * 8 + 4];
        bz[0] = bb0.x; bz[1] = bb0.y; bz[2] = bb0.z; bz[3] = bb0.w;
        bz[4] = bb1.x; bz[5] = bb1.y; bz[6] = bb1.z; bz[7] = bb1.w;
    }
    bool rside = (B0 < 2500);
#pragma unroll
    for (int rp = 0; rp < 4; rp++) {
#pragma unroll
        for (int h = 0; h < 2; h++) {
            int r = ty * 8 + rp * 2 + h;
            int nn = 2 * B0 + (r >> 5);
            int b = r & 31;
            float v[8];
#pragma unroll
            for (int j = 0; j < 8; j++) {
                float lo, hi; upk2(acc[rp][j], lo, hi);
                v[j] = sigf((h ? hi : lo) + bz[j]);
            }
            if (rside) {
                int t = 2 * nn + (tx >> 3);
                int c = (tx & 7) * 8;
                const float* sp = state + (size_t)b * S_STRIDE + t * 64 + c;
                float4 s0 = *(const float4*)sp;
                float4 s1 = *(const float4*)(sp + 4);
                uint4 o;
                ((__half2*)&o)[0] = __floats2half2_rn(v[0] * s0.x, v[1] * s0.y);
                ((__half2*)&o)[1] = __floats2half2_rn(v[2] * s0.z, v[3] * s0.w);
                ((__half2*)&o)[2] = __floats2half2_rn(v[4] * s1.x, v[5] * s1.y);
                ((__half2*)&o)[3] = __floats2half2_rn(v[6] * s1.z, v[7] * s1.w);
                *(uint4*)&g_XSh[(size_t)t * SROW + b * 64 + c] = o;
            } else {
                uint4 o;
                ((__half2*)&o)[0] = __floats2half2_rn(v[0], v[1]);
                ((__half2*)&o)[1] = __floats2half2_rn(v[2], v[3]);
                ((__half2*)&o)[2] = __floats2half2_rn(v[4], v[5]);
                ((__half2*)&o)[3] = __floats2half2_rn(v[6], v[7]);
                __stcs((uint4*)&g_Uh[(size_t)b * S_STRIDE + (nn - 5000) * 128 + tx * 8], o);
            }
        }
    }
}

// ---------------- GEMM2 + GRU combine ----------------
__global__ void __launch_bounds__(128) k_gemm2(const float* __restrict__ w,
                                               const float* __restrict__ bias,
                                               const float* __restrict__ state,
                                               float* __restrict__ out) {
    __shared__ float xs[NF][66];
    __shared__ float ws[NF * NU];
    int tid = threadIdx.x;
    int B0 = blockIdx.x;                 // nodes 2B0, 2B0+1 (rows g0..g0+63)
    for (int i = tid; i < NF * NU; i += 128) ws[i] = w[i];
    fill_xs(xs, tid, B0);
    __syncthreads();
    int tx = tid & 15, ty = tid >> 4;
    ull acc[4][4];
#pragma unroll
    for (int i = 0; i < 4; i++)
#pragma unroll
        for (int j = 0; j < 4; j++) acc[i][j] = 0ull;

#pragma unroll 2
    for (int f = 0; f < NF; f++) {
        ull a[4];
#pragma unroll
        for (int rp = 0; rp < 4; rp++)
            a[rp] = *(const ull*)&xs[f][ty * 8 + rp * 2];
        float4 w4 = *(const float4*)&ws[f * NU + tx * 4];
        ull wd[4];
        wd[0] = pk2(w4.x, w4.x); wd[1] = pk2(w4.y, w4.y);
        wd[2] = pk2(w4.z, w4.z); wd[3] = pk2(w4.w, w4.w);
#pragma unroll
        for (int rp = 0; rp < 4; rp++)
#pragma unroll
            for (int j = 0; j < 4; j++) fma2(acc[rp][j], a[rp], wd[j]);
    }

    float4 bb = *(const float4*)&bias[tx * 4];
    float bz[4] = {bb.x, bb.y, bb.z, bb.w};
#pragma unroll
    for (int rp = 0; rp < 4; rp++) {
#pragma unroll
        for (int h = 0; h < 2; h++) {
            int r = ty * 8 + rp * 2 + h;
            int n = 2 * B0 + (r >> 5), b = r & 31;
            size_t j = (size_t)b * S_STRIDE + n * 64 + tx * 4;
            float c[4];
#pragma unroll
            for (int q = 0; q < 4; q++) {
                float lo, hi; upk2(acc[rp][q], lo, hi);
                c[q] = fmaxf((h ? hi : lo) + bz[q], 0.0f);
            }
            uint2 uh = __ldcs((const uint2*)&g_Uh[j]);
            float2 u0 = __half22float2(*(__half2*)&uh.x);
            float2 u1 = __half22float2(*(__half2*)&uh.y);
            float4 s4 = *(const float4*)&state[j];
            float4 o;
            o.x = u0.x * s4.x + (1.0f - u0.x) * c[0];
            o.y = u0.y * s4.y + (1.0f - u0.y) * c[1];
            o.z = u1.x * s4.z + (1.0f - u1.x) * c[2];
            o.w = u1.y * s4.w + (1.0f - u1.y) * c[3];
            *(float4*)&out[j] = o;
        }
    }
}

// ---------------- launch ----------------
extern "C" void kernel_launch(void* const* d_in, const int* in_sizes, int n_in,
                              void* d_out, int out_size) {
    const float* inputs = (const float*)d_in[0];
    const float* state  = (const float*)d_in[1];
    const int*   m_rows = (const int*)d_in[2];
    const int*   m_cols = (const int*)d_in[3];
    const float* m_vals = (const float*)d_in[4];
    const float* w1     = (const float*)d_in[5];
    const float* b1     = (const float*)d_in[6];
    const float* w2     = (const float*)d_in[7];
    const float* b2     = (const float*)d_in[8];
    float* out = (float*)d_out;
    int nnz = in_sizes[2];

    k_zero<<<(N_NODES + 255) / 256, 256>>>();
    k_hist<<<(nnz + 255) / 256, 256>>>(m_rows, nnz);
    k_scan<<<1, 1024>>>();
    k_scatter<<<(nnz + 255) / 256, 256>>>(m_rows, m_cols, m_vals, nnz);

    k_buildXS<<<(XS_ELEMS / 8 + 255) / 256, 256>>>(state);
    k_buildXI<<<(N_NODES * NB + 255) / 256, 256>>>(inputs);
    k_spmm_in<<<(N_NODES * 32 + 255) / 256, 256>>>();   // YI, reused by both gc's

    k_spmm_s<<<N_NODES, 256>>>();
    k_gemm1f<<<N_NODES / 2, 128>>>(w1, b1, state);      // rewrites g_XSh (r*state), writes g_Uh
    k_spmm_s<<<N_NODES, 256>>>();
    k_gemm2<<<N_NODES / 2, 128>>>(w2, b2, state, out);
}

// round 4
// speedup vs baseline: 1.7955x; 1.0441x over previous
#include <cuda_runtime.h>
#include <cuda_fp16.h>

#define N_NODES 10000
#define NB 32
#define NF 66
#define NU 64
#define NU2 128
#define SROW 2048            // halves per node state-row
#define SROWQ 256            // uint4 per state-row
#define NNZ_MAX 330000
#define XS_ELEMS (N_NODES * SROW)
#define S_STRIDE 640000      // N*NU per batch

typedef unsigned long long ull;

__device__ __half  g_XSh[XS_ELEMS];        // 41 MB gather source (state part)
__device__ __half  g_X1h[XS_ELEMS];        // 41 MB spmm output
__device__ float2  g_XI[N_NODES * NB];     // inputs-part gather source (fp32)
__device__ float2  g_YI[N_NODES * NB];     // inputs-part spmm result (reused)
__device__ __half  g_Uh[NB * S_STRIDE];    // 41 MB update gate
__device__ int     g_cnt[N_NODES];
__device__ int     g_cur[N_NODES];
__device__ int     g_rowptr[N_NODES + 1];
__device__ int     g_col[NNZ_MAX];
__device__ float   g_val[NNZ_MAX];

// ---------- streams/events for in-capture forks (created at static init) ----------
static cudaStream_t g_s1;
static cudaEvent_t  g_evFork, g_evBuild, g_evCsr, g_evIn;
namespace {
struct HxInit {
    HxInit() {
        cudaStreamCreateWithFlags(&g_s1, cudaStreamNonBlocking);
        cudaEventCreateWithFlags(&g_evFork,  cudaEventDisableTiming);
        cudaEventCreateWithFlags(&g_evBuild, cudaEventDisableTiming);
        cudaEventCreateWithFlags(&g_evCsr,   cudaEventDisableTiming);
        cudaEventCreateWithFlags(&g_evIn,    cudaEventDisableTiming);
    }
};
static HxInit g_hxinit;
}

// ---------- f32x2 helpers ----------
__device__ __forceinline__ ull pk2(float lo, float hi) {
    ull r; asm("mov.b64 %0, {%1, %2};" : "=l"(r) : "f"(lo), "f"(hi)); return r;
}
__device__ __forceinline__ void upk2(ull v, float& lo, float& hi) {
    asm("mov.b64 {%0, %1}, %2;" : "=f"(lo), "=f"(hi) : "l"(v));
}
__device__ __forceinline__ void fma2(ull& d, ull a, ull b) {
    asm("fma.rn.f32x2 %0, %1, %2, %0;" : "+l"(d) : "l"(a), "l"(b));
}
__device__ __forceinline__ float sigf(float x) { return 1.0f / (1.0f + __expf(-x)); }

// ---------------- CSR build ----------------
__global__ void k_zero() {
    int i = blockIdx.x * blockDim.x + threadIdx.x;
    if (i < N_NODES) { g_cnt[i] = 0; g_cur[i] = 0; }
}
__global__ void k_hist(const int* __restrict__ rows, int nnz) {
    int i = blockIdx.x * blockDim.x + threadIdx.x;
    if (i < nnz) atomicAdd(&g_cnt[rows[i]], 1);
}
__global__ void k_scan() {
    __shared__ int s[1024];
    int tid = threadIdx.x;
    int loc[10];
    int sum = 0;
#pragma unroll
    for (int k = 0; k < 10; k++) {
        int i = tid * 10 + k;
        int v = (i < N_NODES) ? g_cnt[i] : 0;
        loc[k] = v; sum += v;
    }
    s[tid] = sum;
    __syncthreads();
    for (int d = 1; d < 1024; d <<= 1) {
        int v = (tid >= d) ? s[tid - d] : 0;
        __syncthreads();
        s[tid] += v;
        __syncthreads();
    }
    int run = s[tid] - sum;
#pragma unroll
    for (int k = 0; k < 10; k++) {
        int i = tid * 10 + k;
        if (i < N_NODES) g_rowptr[i] = run;
        run += loc[k];
    }
    if (tid == 1023) g_rowptr[N_NODES] = run;
}
__global__ void k_scatter(const int* __restrict__ rows, const int* __restrict__ cols,
                          const float* __restrict__ vals, int nnz) {
    int i = blockIdx.x * blockDim.x + threadIdx.x;
    if (i < nnz) {
        int r = rows[i];
        int p = g_rowptr[r] + atomicAdd(&g_cur[r], 1);
        g_col[p] = cols[i];
        g_val[p] = vals[i];
    }
}

// ---------------- fused builder (XS fp16 + XI) ----------------
#define XS_Q (XS_ELEMS / 8)
__global__ void k_build(const float* __restrict__ inputs, const float* __restrict__ state) {
    int id = blockIdx.x * 256 + threadIdx.x;
    if (id < XS_Q) {
        int i8 = id * 8;
        int n = i8 >> 11;
        int b = (i8 >> 6) & 31;
        int u = i8 & 63;
        const float* sp = state + (size_t)b * S_STRIDE + n * 64 + u;
        float4 s0 = *(const float4*)sp;
        float4 s1 = *(const float4*)(sp + 4);
        uint4 o;
        ((__half2*)&o)[0] = __floats2half2_rn(s0.x, s0.y);
        ((__half2*)&o)[1] = __floats2half2_rn(s0.z, s0.w);
        ((__half2*)&o)[2] = __floats2half2_rn(s1.x, s1.y);
        ((__half2*)&o)[3] = __floats2half2_rn(s1.z, s1.w);
        ((uint4*)g_XSh)[id] = o;
    } else {
        int j = id - XS_Q;
        if (j < N_NODES * NB) {
            int b = j / N_NODES, n = j - b * N_NODES;
            float2 v = *(const float2*)&inputs[b * 20000 + 2 * n];
            g_XI[n * 32 + b] = v;
        }
    }
}

// ---------------- SpMM (inputs part, once) ----------------
__global__ void k_spmm_in() {
    int gw = (blockIdx.x * 256 + threadIdx.x) >> 5;
    int lane = threadIdx.x & 31;
    if (gw >= N_NODES) return;
    int beg = __ldg(&g_rowptr[gw]), end = __ldg(&g_rowptr[gw + 1]);
    float2 acc = make_float2(0.f, 0.f);
    for (int e = beg; e < end; e++) {
        int c = __ldg(&g_col[e]);
        float v = __ldg(&g_val[e]);
        float2 x = g_XI[c * 32 + lane];
        acc.x = fmaf(v, x.x, acc.x);
        acc.y = fmaf(v, x.y, acc.y);
    }
    g_YI[gw * 32 + lane] = acc;
}

// ---------------- SpMM (state part): 2 blocks/row, 128 threads ----------------
__device__ __forceinline__ void acc8(float* a, uint4 q, float v) {
    float2 f0 = __half22float2(*(__half2*)&q.x);
    float2 f1 = __half22float2(*(__half2*)&q.y);
    float2 f2 = __half22float2(*(__half2*)&q.z);
    float2 f3 = __half22float2(*(__half2*)&q.w);
    a[0] = fmaf(v, f0.x, a[0]); a[1] = fmaf(v, f0.y, a[1]);
    a[2] = fmaf(v, f1.x, a[2]); a[3] = fmaf(v, f1.y, a[3]);
    a[4] = fmaf(v, f2.x, a[4]); a[5] = fmaf(v, f2.y, a[5]);
    a[6] = fmaf(v, f3.x, a[6]); a[7] = fmaf(v, f3.y, a[7]);
}

__global__ void __launch_bounds__(128, 10) k_spmm_s() {
    const uint4* __restrict__ X = (const uint4*)g_XSh;
    int n = blockIdx.x >> 1;
    int slot = ((blockIdx.x & 1) << 7) + threadIdx.x;   // uint4 index within row
    int t = threadIdx.x;
    __shared__ int   scol[128];
    __shared__ float sval[128];
    float a[8] = {0.f, 0.f, 0.f, 0.f, 0.f, 0.f, 0.f, 0.f};
    int beg = __ldg(&g_rowptr[n]), end = __ldg(&g_rowptr[n + 1]);
    for (int base = beg; base < end; base += 128) {
        int cnt = min(128, end - base);
        __syncthreads();
        if (t < cnt) { scol[t] = g_col[base + t]; sval[t] = g_val[base + t]; }
        __syncthreads();
        int e = 0;
        for (; e + 4 <= cnt; e += 4) {
            uint4 q0 = X[(size_t)scol[e + 0] * SROWQ + slot];
            uint4 q1 = X[(size_t)scol[e + 1] * SROWQ + slot];
            uint4 q2 = X[(size_t)scol[e + 2] * SROWQ + slot];
            uint4 q3 = X[(size_t)scol[e + 3] * SROWQ + slot];
            acc8(a, q0, sval[e + 0]);
            acc8(a, q1, sval[e + 1]);
            acc8(a, q2, sval[e + 2]);
            acc8(a, q3, sval[e + 3]);
        }
        for (; e < cnt; e++) {
            uint4 q = X[(size_t)scol[e] * SROWQ + slot];
            acc8(a, q, sval[e]);
        }
    }
    uint4 o;
    ((__half2*)&o)[0] = __floats2half2_rn(a[0], a[1]);
    ((__half2*)&o)[1] = __floats2half2_rn(a[2], a[3]);
    ((__half2*)&o)[2] = __floats2half2_rn(a[4], a[5]);
    ((__half2*)&o)[3] = __floats2half2_rn(a[6], a[7]);
    ((uint4*)g_X1h)[(size_t)n * SROWQ + slot] = o;
}

// ---------------- shared xs fill (conflict-free, padded stride 66) ----------------
__device__ __forceinline__ void fill_xs(float xs[NF][66], int tid, int B0) {
    const uint2* src = (const uint2*)(g_X1h + (size_t)B0 * 4096);
#pragma unroll
    for (int k = 0; k < 8; k++) {
        int idx4 = tid + k * 128;        // 1024 uint2 = 64 rows x 16
        int r = idx4 >> 4;
        int u = (idx4 & 15) * 4;
        uint2 q = src[idx4];
        float2 f0 = __half22float2(*(__half2*)&q.x);
        float2 f1 = __half22float2(*(__half2*)&q.y);
        xs[u + 2][r] = f0.x; xs[u + 3][r] = f0.y;
        xs[u + 4][r] = f1.x; xs[u + 5][r] = f1.y;
    }
    {   // inputs-part columns from precomputed YI
        int r = tid >> 1, f = tid & 1;
        int node = 2 * B0 + (r >> 5), b = r & 31;
        float2 y = g_YI[node * 32 + b];
        xs[f][r] = f ? y.y : y.x;
    }
}

// ---------------- GEMM1 fused: sigmoid; write r*state (fp16) or u (fp16) ----------------
__global__ void __launch_bounds__(128) k_gemm1f(const float* __restrict__ w,
                                                const float* __restrict__ bias) {
    __shared__ float xs[NF][66];
    __shared__ float ws[NF * NU2];
    int tid = threadIdx.x;
    int B0 = blockIdx.x;                 // nodes 2B0, 2B0+1
    for (int i = tid; i < NF * NU2; i += 128) ws[i] = w[i];
    fill_xs(xs, tid, B0);
    __syncthreads();
    int tx = tid & 15, ty = tid >> 4;
    ull acc[4][8];
#pragma unroll
    for (int i = 0; i < 4; i++)
#pragma unroll
        for (int j = 0; j < 8; j++) acc[i][j] = 0ull;

#pragma unroll 2
    for (int f = 0; f < NF; f++) {
        ull a[4];
#pragma unroll
        for (int rp = 0; rp < 4; rp++)
            a[rp] = *(const ull*)&xs[f][ty * 8 + rp * 2];
        float4 w0 = *(const float4*)&ws[f * NU2 + tx * 8];
        float4 w1 = *(const float4*)&ws[f * NU2 + tx * 8 + 4];
        ull wd[8];
        wd[0] = pk2(w0.x, w0.x); wd[1] = pk2(w0.y, w0.y);
        wd[2] = pk2(w0.z, w0.z); wd[3] = pk2(w0.w, w0.w);
        wd[4] = pk2(w1.x, w1.x); wd[5] = pk2(w1.y, w1.y);
        wd[6] = pk2(w1.z, w1.z); wd[7] = pk2(w1.w, w1.w);
#pragma unroll
        for (int rp = 0; rp < 4; rp++)
#pragma unroll
            for (int j = 0; j < 8; j++) fma2(acc[rp][j], a[rp], wd[j]);
    }

    float bz[8];
    {
        float4 bb0 = *(const float4*)&bias[tx * 8];
        float4 bb1 = *(const float4*)&bias[tx * 8 + 4];
        bz[0] = bb0.x; bz[1] = bb0.y; bz[2] = bb0.z; bz[3] = bb0.w;
        bz[4] = bb1.x; bz[5] = bb1.y; bz[6] = bb1.z; bz[7] = bb1.w;
    }
    bool rside = (B0 < 2500);
#pragma unroll
    for (int rp = 0; rp < 4; rp++) {
#pragma unroll
        for (int h = 0; h < 2; h++) {
            int r = ty * 8 + rp * 2 + h;
            int nn = 2 * B0 + (r >> 5);
            int b = r & 31;
            float v[8];
#pragma unroll
            for (int j = 0; j < 8; j++) {
                float lo, hi; upk2(acc[rp][j], lo, hi);
                v[j] = sigf((h ? hi : lo) + bz[j]);
            }
            if (rside) {
                int t = 2 * nn + (tx >> 3);
                int c = (tx & 7) * 8;
                // state (fp16) lives in g_XSh until this thread overwrites it;
                // each octet is read+written by exactly one thread.
                uint4* addr = (uint4*)&g_XSh[(size_t)t * SROW + b * 64 + c];
                uint4 sh = *addr;
                float2 s0 = __half22float2(((__half2*)&sh)[0]);
                float2 s1 = __half22float2(((__half2*)&sh)[1]);
                float2 s2 = __half22float2(((__half2*)&sh)[2]);
                float2 s3 = __half22float2(((__half2*)&sh)[3]);
                uint4 o;
                ((__half2*)&o)[0] = __floats2half2_rn(v[0] * s0.x, v[1] * s0.y);
                ((__half2*)&o)[1] = __floats2half2_rn(v[2] * s1.x, v[3] * s1.y);
                ((__half2*)&o)[2] = __floats2half2_rn(v[4] * s2.x, v[5] * s2.y);
                ((__half2*)&o)[3] = __floats2half2_rn(v[6] * s3.x, v[7] * s3.y);
                *addr = o;
            } else {
                uint4 o;
                ((__half2*)&o)[0] = __floats2half2_rn(v[0], v[1]);
                ((__half2*)&o)[1] = __floats2half2_rn(v[2], v[3]);
                ((__half2*)&o)[2] = __floats2half2_rn(v[4], v[5]);
                ((__half2*)&o)[3] = __floats2half2_rn(v[6], v[7]);
                __stcs((uint4*)&g_Uh[(size_t)b * S_STRIDE + (nn - 5000) * 128 + tx * 8], o);
            }
        }
    }
}

// ---------------- GEMM2 + GRU combine ----------------
__global__ void __launch_bounds__(128) k_gemm2(const float* __restrict__ w,
                                               const float* __restrict__ bias,
                                               const float* __restrict__ state,
                                               float* __restrict__ out) {
    __shared__ float xs[NF][66];
    __shared__ float ws[NF * NU];
    int tid = threadIdx.x;
    int B0 = blockIdx.x;
    for (int i = tid; i < NF * NU; i += 128) ws[i] = w[i];
    fill_xs(xs, tid, B0);
    __syncthreads();
    int tx = tid & 15, ty = tid >> 4;
    ull acc[4][4];
#pragma unroll
    for (int i = 0; i < 4; i++)
#pragma unroll
        for (int j = 0; j < 4; j++) acc[i][j] = 0ull;

#pragma unroll 2
    for (int f = 0; f < NF; f++) {
        ull a[4];
#pragma unroll
        for (int rp = 0; rp < 4; rp++)
            a[rp] = *(const ull*)&xs[f][ty * 8 + rp * 2];
        float4 w4 = *(const float4*)&ws[f * NU + tx * 4];
        ull wd[4];
        wd[0] = pk2(w4.x, w4.x); wd[1] = pk2(w4.y, w4.y);
        wd[2] = pk2(w4.z, w4.z); wd[3] = pk2(w4.w, w4.w);
#pragma unroll
        for (int rp = 0; rp < 4; rp++)
#pragma unroll
            for (int j = 0; j < 4; j++) fma2(acc[rp][j], a[rp], wd[j]);
    }

    float4 bb = *(const float4*)&bias[tx * 4];
    float bz[4] = {bb.x, bb.y, bb.z, bb.w};
#pragma unroll
    for (int rp = 0; rp < 4; rp++) {
#pragma unroll
        for (int h = 0; h < 2; h++) {
            int r = ty * 8 + rp * 2 + h;
            int n = 2 * B0 + (r >> 5), b = r & 31;
            size_t j = (size_t)b * S_STRIDE + n * 64 + tx * 4;
            float c[4];
#pragma unroll
            for (int q = 0; q < 4; q++) {
                float lo, hi; upk2(acc[rp][q], lo, hi);
                c[q] = fmaxf((h ? hi : lo) + bz[q], 0.0f);
            }
            uint2 uh = __ldcs((const uint2*)&g_Uh[j]);
            float2 u0 = __half22float2(*(__half2*)&uh.x);
            float2 u1 = __half22float2(*(__half2*)&uh.y);
            float4 s4 = *(const float4*)&state[j];
            float4 o;
            o.x = u0.x * s4.x + (1.0f - u0.x) * c[0];
            o.y = u0.y * s4.y + (1.0f - u0.y) * c[1];
            o.z = u1.x * s4.z + (1.0f - u1.x) * c[2];
            o.w = u1.y * s4.w + (1.0f - u1.y) * c[3];
            *(float4*)&out[j] = o;
        }
    }
}

// ---------------- launch ----------------
extern "C" void kernel_launch(void* const* d_in, const int* in_sizes, int n_in,
                              void* d_out, int out_size) {
    const float* inputs = (const float*)d_in[0];
    const float* state  = (const float*)d_in[1];
    const int*   m_rows = (const int*)d_in[2];
    const int*   m_cols = (const int*)d_in[3];
    const float* m_vals = (const float*)d_in[4];
    const float* w1     = (const float*)d_in[5];
    const float* b1     = (const float*)d_in[6];
    const float* w2     = (const float*)d_in[7];
    const float* b2     = (const float*)d_in[8];
    float* out = (float*)d_out;
    int nnz = in_sizes[2];

    // fork: builder runs on side stream in parallel with CSR chain
    cudaEventRecord(g_evFork, 0);
    cudaStreamWaitEvent(g_s1, g_evFork, 0);
    k_build<<<(XS_Q + N_NODES * NB + 255) / 256, 256, 0, g_s1>>>(inputs, state);
    cudaEventRecord(g_evBuild, g_s1);

    k_zero<<<(N_NODES + 255) / 256, 256>>>();
    k_hist<<<(nnz + 255) / 256, 256>>>(m_rows, nnz);
    k_scan<<<1, 1024>>>();
    k_scatter<<<(nnz + 255) / 256, 256>>>(m_rows, m_cols, m_vals, nnz);

    // side: inputs-part SpMM overlaps the first big SpMM (needs CSR + build)
    cudaEventRecord(g_evCsr, 0);
    cudaStreamWaitEvent(g_s1, g_evCsr, 0);
    k_spmm_in<<<(N_NODES * 32 + 255) / 256, 256, 0, g_s1>>>();
    cudaEventRecord(g_evIn, g_s1);

    cudaStreamWaitEvent(0, g_evBuild, 0);
    k_spmm_s<<<2 * N_NODES, 128>>>();
    cudaStreamWaitEvent(0, g_evIn, 0);
    k_gemm1f<<<N_NODES / 2, 128>>>(w1, b1);     // rewrites g_XSh (r*state), writes g_Uh
    k_spmm_s<<<2 * N_NODES, 128>>>();
    k_gemm2<<<N_NODES / 2, 128>>>(w2, b2, state, out);
}